// round 4
// baseline (speedup 1.0000x reference)
#include <cuda_runtime.h>

#define N_NODES 100000
#define N_EDGES 1600000
#define DIM 128
#define NLAYER 5

// ---------------- scratch (device globals; no allocations) ----------------
__device__ float g_h[N_NODES * DIM];
__device__ float g_agg[N_NODES * DIM];
__device__ float g_mid[N_NODES * 2 * DIM];
__device__ int   g_rowptr[N_NODES + 1];
__device__ int   g_cursor[N_NODES];
__device__ int   g_cnt[N_NODES];
__device__ int   g_edge[N_EDGES];             // packed: src | combined_idx<<20

#define W1T_SZ (NLAYER * 128 * 512)           // [l][k][2j] duplicated, J=256
#define W2T_SZ (NLAYER * 256 * 256)           // [l][k][2j] duplicated, J=128
__device__ float g_w1t[W1T_SZ];
__device__ float g_w2t[W2T_SZ];

// ---------------- weight pre-transpose + pair-duplicate ----------------
__global__ void k_wt(const float* __restrict__ w1, const float* __restrict__ w2) {
    int i = blockIdx.x * blockDim.x + threadIdx.x;
    if (i < W1T_SZ) {
        int l = i / (128 * 512);
        int r = i - l * 128 * 512;
        int k = r >> 9, jj = r & 511;
        g_w1t[i] = w1[((size_t)l * 256 + (jj >> 1)) * 128 + k];
    }
    if (i < W2T_SZ) {
        int l = i / (256 * 256);
        int r = i - l * 65536;
        int k = r >> 8, jj = r & 255;
        g_w2t[i] = w2[((size_t)l * 128 + (jj >> 1)) * 256 + k];
    }
}

// ---------------- CSR build ----------------
__global__ void k_zero_cnt(int n) {
    int i = blockIdx.x * blockDim.x + threadIdx.x;
    if (i < n) g_cnt[i] = 0;
}

__global__ void k_count(const int* __restrict__ dst, int E) {
    int e = blockIdx.x * blockDim.x + threadIdx.x;
    if (e < E) atomicAdd(&g_cnt[dst[e]], 1);
}

__global__ void k_scan(int n) {
    __shared__ int wsum[32];
    __shared__ int carry_s;
    if (threadIdx.x == 0) carry_s = 0;
    __syncthreads();
    int lane = threadIdx.x & 31, wid = threadIdx.x >> 5;
    for (int base = 0; base < n; base += 1024) {
        int i = base + threadIdx.x;
        int v = (i < n) ? g_cnt[i] : 0;
        int s = v;
        #pragma unroll
        for (int o = 1; o < 32; o <<= 1) {
            int t = __shfl_up_sync(0xffffffffu, s, o);
            if (lane >= o) s += t;
        }
        if (lane == 31) wsum[wid] = s;
        __syncthreads();
        if (wid == 0) {
            int ws = wsum[lane];
            #pragma unroll
            for (int o = 1; o < 32; o <<= 1) {
                int t = __shfl_up_sync(0xffffffffu, ws, o);
                if (lane >= o) ws += t;
            }
            wsum[lane] = ws;
        }
        __syncthreads();
        int excl = s - v + (wid ? wsum[wid - 1] : 0) + carry_s;
        if (i < n) { g_rowptr[i] = excl; g_cursor[i] = excl; }
        __syncthreads();
        if (threadIdx.x == 1023) carry_s = excl + v;
        __syncthreads();
    }
    if (threadIdx.x == 0) g_rowptr[n] = carry_s;
}

__global__ void k_fill(const int* __restrict__ src, const int* __restrict__ dst,
                       const int* __restrict__ eattr, int E) {
    int e = blockIdx.x * blockDim.x + threadIdx.x;
    if (e >= E) return;
    int d = dst[e];
    int pos = atomicAdd(&g_cursor[d], 1);
    int ci = eattr[2 * e] * 3 + eattr[2 * e + 1];
    g_edge[pos] = src[e] | (ci << 20);
}

// ---------------- node input embedding ----------------
__global__ void k_embed(const int* __restrict__ x, const float* __restrict__ xemb, int n) {
    int i = blockIdx.x * blockDim.x + threadIdx.x;
    int v = i >> 5, c = (i & 31) * 4;
    if (v >= n) return;
    int a = x[2 * v], ch = x[2 * v + 1];
    float4 va = *(const float4*)(xemb + (size_t)a * DIM + c);
    float4 vb = *(const float4*)(xemb + (size_t)(120 + ch) * DIM + c);
    float4 r;
    r.x = va.x + vb.x; r.y = va.y + vb.y; r.z = va.z + vb.z; r.w = va.w + vb.w;
    *(float4*)(g_h + (size_t)v * DIM + c) = r;
}

// ---------------- aggregation: one warp per node, combined edge table ----------------
__global__ void k_agg(const float* __restrict__ etab_l, int n) {
    __shared__ float4 ctb[18 * 32];
    for (int i = threadIdx.x; i < 18 * 32; i += blockDim.x) {
        int comb = i >> 5, ln = i & 31;
        int eb = comb / 3, ed = comb - eb * 3;
        float4 b = ((const float4*)etab_l)[eb * 32 + ln];
        float4 d = ((const float4*)(etab_l + 6 * DIM))[ed * 32 + ln];
        ctb[i] = make_float4(b.x + d.x, b.y + d.y, b.z + d.z, b.w + d.w);
    }
    __syncthreads();
    int w = (blockIdx.x * blockDim.x + threadIdx.x) >> 5;
    int lane = threadIdx.x & 31;
    if (w >= n) return;
    int beg = g_rowptr[w], end = g_rowptr[w + 1];
    float4 acc0 = *(const float4*)(g_h + (size_t)w * DIM + lane * 4);
    {
        float4 sl = ctb[12 * 32 + lane];   // self-loop: bond 4, dir 0
        acc0.x += sl.x; acc0.y += sl.y; acc0.z += sl.z; acc0.w += sl.w;
    }
    float4 acc1 = make_float4(0.f, 0.f, 0.f, 0.f);
    float4 acc2 = make_float4(0.f, 0.f, 0.f, 0.f);
    float4 acc3 = make_float4(0.f, 0.f, 0.f, 0.f);
    int p = beg;
    for (; p + 4 <= end; p += 4) {
        int pk0 = g_edge[p], pk1 = g_edge[p + 1], pk2 = g_edge[p + 2], pk3 = g_edge[p + 3];
        float4 h0 = *(const float4*)(g_h + (size_t)(pk0 & 0xFFFFF) * DIM + lane * 4);
        float4 h1 = *(const float4*)(g_h + (size_t)(pk1 & 0xFFFFF) * DIM + lane * 4);
        float4 h2 = *(const float4*)(g_h + (size_t)(pk2 & 0xFFFFF) * DIM + lane * 4);
        float4 h3 = *(const float4*)(g_h + (size_t)(pk3 & 0xFFFFF) * DIM + lane * 4);
        float4 e0 = ctb[(pk0 >> 20) * 32 + lane];
        float4 e1 = ctb[(pk1 >> 20) * 32 + lane];
        float4 e2 = ctb[(pk2 >> 20) * 32 + lane];
        float4 e3 = ctb[(pk3 >> 20) * 32 + lane];
        acc0.x += h0.x + e0.x; acc0.y += h0.y + e0.y; acc0.z += h0.z + e0.z; acc0.w += h0.w + e0.w;
        acc1.x += h1.x + e1.x; acc1.y += h1.y + e1.y; acc1.z += h1.z + e1.z; acc1.w += h1.w + e1.w;
        acc2.x += h2.x + e2.x; acc2.y += h2.y + e2.y; acc2.z += h2.z + e2.z; acc2.w += h2.w + e2.w;
        acc3.x += h3.x + e3.x; acc3.y += h3.y + e3.y; acc3.z += h3.z + e3.z; acc3.w += h3.w + e3.w;
    }
    for (; p < end; p++) {
        int pk = g_edge[p];
        float4 hv = *(const float4*)(g_h + (size_t)(pk & 0xFFFFF) * DIM + lane * 4);
        float4 ev = ctb[(pk >> 20) * 32 + lane];
        acc0.x += hv.x + ev.x; acc0.y += hv.y + ev.y;
        acc0.z += hv.z + ev.z; acc0.w += hv.w + ev.w;
    }
    acc0.x += acc1.x + acc2.x + acc3.x;
    acc0.y += acc1.y + acc2.y + acc3.y;
    acc0.z += acc1.z + acc2.z + acc3.z;
    acc0.w += acc1.w + acc2.w + acc3.w;
    *(float4*)(g_agg + (size_t)w * DIM + lane * 4) = acc0;
}

// ---------------- GEMM: C[M,JTOT] = A[M,K] @ W[JTOT,K]^T ----------------
// Wt is the pre-transposed, pair-duplicated weight: Wt[k][2j]=Wt[k][2j+1]=W[j][k],
// row stride 2*JTOT. B staging is a straight coalesced copy (no conflicts).
__device__ __forceinline__ void ffma2(unsigned long long& d, unsigned long long a,
                                      unsigned long long b) {
    asm("fma.rn.f32x2 %0, %1, %2, %0;" : "+l"(d) : "l"(a), "l"(b));
}

#define AS_STRIDE 132
#define BS_STRIDE 260
#define GEMM_SMEM ((64 * AS_STRIDE + 64 * BS_STRIDE) * 4)

template <int K, int JTOT, bool BN, bool RELU>
__launch_bounds__(256, 2)
__global__ void k_gemm(const float* __restrict__ A, const float* __restrict__ Wt,
                       const float* __restrict__ bias,
                       const float* __restrict__ gamma, const float* __restrict__ beta,
                       const float* __restrict__ mean, const float* __restrict__ var,
                       float* __restrict__ C, int M) {
    extern __shared__ float sm[];
    float* As = sm;                      // [64][AS_STRIDE] k-major
    float* Bs = sm + 64 * AS_STRIDE;     // [64][BS_STRIDE] pair-duplicated
    int tid = threadIdx.x;
    int tc = tid & 15, tr = tid >> 4;
    int mb = blockIdx.x, jbase = blockIdx.y * 128;
    int jb2 = 2 * jbase;

    unsigned long long acc[32];
    #pragma unroll
    for (int i = 0; i < 32; i++) acc[i] = 0ull;

    for (int kb = 0; kb < K; kb += 64) {
        // stage A: 128 rows x 64 k, float2 loads (coalesced), 4-way-conflict stores
        #pragma unroll
        for (int t = 0; t < 16; t++) {
            int idx = tid + t * 256;          // 0..4095
            int kq2 = idx & 31;               // k-pair
            int row = idx >> 5;               // 0..127
            int rg = mb * 128 + row;
            float2 a = (rg < M) ? *(const float2*)(A + (size_t)rg * K + kb + kq2 * 2)
                                : make_float2(0.f, 0.f);
            As[(kq2 * 2) * AS_STRIDE + row]     = a.x;
            As[(kq2 * 2 + 1) * AS_STRIDE + row] = a.y;
        }
        // stage B: straight coalesced copy of pre-duplicated weights
        #pragma unroll
        for (int t = 0; t < 16; t++) {
            int idx = tid + t * 256;          // 0..4095
            int f4 = idx & 63;
            int k  = idx >> 6;
            *(float4*)(Bs + k * BS_STRIDE + f4 * 4) =
                *(const float4*)(Wt + (size_t)(kb + k) * (2 * JTOT) + jb2 + f4 * 4);
        }
        __syncthreads();
        #pragma unroll 8
        for (int k = 0; k < 64; k++) {
            const unsigned long long* ap =
                (const unsigned long long*)(As + k * AS_STRIDE) + tr * 4;
            const unsigned long long* bp =
                (const unsigned long long*)(Bs + k * BS_STRIDE) + tc;
            unsigned long long a0 = ap[0], a1 = ap[1], a2 = ap[2], a3 = ap[3];
            unsigned long long b0 = bp[0],  b1 = bp[16],  b2 = bp[32],  b3 = bp[48];
            unsigned long long b4 = bp[64], b5 = bp[80],  b6 = bp[96],  b7 = bp[112];
            ffma2(acc[0],  a0, b0); ffma2(acc[1],  a0, b1);
            ffma2(acc[2],  a0, b2); ffma2(acc[3],  a0, b3);
            ffma2(acc[4],  a0, b4); ffma2(acc[5],  a0, b5);
            ffma2(acc[6],  a0, b6); ffma2(acc[7],  a0, b7);
            ffma2(acc[8],  a1, b0); ffma2(acc[9],  a1, b1);
            ffma2(acc[10], a1, b2); ffma2(acc[11], a1, b3);
            ffma2(acc[12], a1, b4); ffma2(acc[13], a1, b5);
            ffma2(acc[14], a1, b6); ffma2(acc[15], a1, b7);
            ffma2(acc[16], a2, b0); ffma2(acc[17], a2, b1);
            ffma2(acc[18], a2, b2); ffma2(acc[19], a2, b3);
            ffma2(acc[20], a2, b4); ffma2(acc[21], a2, b5);
            ffma2(acc[22], a2, b6); ffma2(acc[23], a2, b7);
            ffma2(acc[24], a3, b0); ffma2(acc[25], a3, b1);
            ffma2(acc[26], a3, b2); ffma2(acc[27], a3, b3);
            ffma2(acc[28], a3, b4); ffma2(acc[29], a3, b5);
            ffma2(acc[30], a3, b6); ffma2(acc[31], a3, b7);
        }
        __syncthreads();
    }

    // fused epilogue: bias (+ BN) (+ ReLU); thread's columns: jbase + c*16 + tc
    float cs[8], csh[8];
    #pragma unroll
    for (int c = 0; c < 8; c++) {
        int j = jbase + c * 16 + tc;
        if (BN) {
            float s = gamma[j] * rsqrtf(var[j] + 1e-5f);
            cs[c] = s;
            csh[c] = (bias[j] - mean[j]) * s + beta[j];
        } else {
            cs[c] = 1.f;
            csh[c] = bias[j];
        }
    }
    #pragma unroll
    for (int rp = 0; rp < 4; rp++) {
        #pragma unroll
        for (int h = 0; h < 2; h++) {
            int row = mb * 128 + tr * 8 + rp * 2 + h;
            if (row < M) {
                float* outp = C + (size_t)row * JTOT + jbase + tc;
                #pragma unroll
                for (int c = 0; c < 8; c++) {
                    unsigned long long u = acc[rp * 8 + c];
                    unsigned int bits = h ? (unsigned int)(u >> 32) : (unsigned int)u;
                    float v = __uint_as_float(bits);
                    v = v * cs[c] + csh[c];
                    if (RELU) v = fmaxf(v, 0.f);
                    outp[c * 16] = v;
                }
            }
        }
    }
}

// ---------------- launch ----------------
extern "C" void kernel_launch(void* const* d_in, const int* in_sizes, int n_in,
                              void* d_out, int out_size) {
    const int*   x     = (const int*)d_in[0];
    const int*   eidx  = (const int*)d_in[1];
    const int*   eattr = (const int*)d_in[2];
    const float* xemb  = (const float*)d_in[3];
    const float* etab  = (const float*)d_in[4];
    const float* w1    = (const float*)d_in[5];
    const float* b1    = (const float*)d_in[6];
    const float* w2    = (const float*)d_in[7];
    const float* b2    = (const float*)d_in[8];
    const float* gamma = (const float*)d_in[9];
    const float* beta  = (const float*)d_in[10];
    const float* bnm   = (const float*)d_in[11];
    const float* bnv   = (const float*)d_in[12];
    float* out = (float*)d_out;

    int n = in_sizes[0] / 2;
    int E = in_sizes[1] / 2;
    const int* srcp = eidx;
    const int* dstp = eidx + E;

    cudaFuncSetAttribute(k_gemm<128, 256, false, true>,
                         cudaFuncAttributeMaxDynamicSharedMemorySize, GEMM_SMEM);
    cudaFuncSetAttribute(k_gemm<256, 128, true, true>,
                         cudaFuncAttributeMaxDynamicSharedMemorySize, GEMM_SMEM);
    cudaFuncSetAttribute(k_gemm<256, 128, true, false>,
                         cudaFuncAttributeMaxDynamicSharedMemorySize, GEMM_SMEM);

    void *ph, *pagg, *pmid, *pw1t, *pw2t;
    cudaGetSymbolAddress(&ph, g_h);
    cudaGetSymbolAddress(&pagg, g_agg);
    cudaGetSymbolAddress(&pmid, g_mid);
    cudaGetSymbolAddress(&pw1t, g_w1t);
    cudaGetSymbolAddress(&pw2t, g_w2t);
    float* H = (float*)ph;
    float* AG = (float*)pagg;
    float* MID = (float*)pmid;
    const float* W1T = (const float*)pw1t;
    const float* W2T = (const float*)pw2t;

    // weight transpose + CSR build + embed
    k_wt<<<(W1T_SZ + 255) / 256, 256>>>(w1, w2);
    k_zero_cnt<<<(n + 255) / 256, 256>>>(n);
    k_count<<<(E + 255) / 256, 256>>>(dstp, E);
    k_scan<<<1, 1024>>>(n);
    k_fill<<<(E + 255) / 256, 256>>>(srcp, dstp, eattr, E);
    k_embed<<<(n * 32 + 255) / 256, 256>>>(x, xemb, n);

    int mblocks = (n + 127) / 128;
    for (int l = 0; l < NLAYER; l++) {
        k_agg<<<(n * 32 + 255) / 256, 256>>>(etab + (size_t)l * 9 * DIM, n);
        k_gemm<128, 256, false, true><<<dim3(mblocks, 2), 256, GEMM_SMEM>>>(
            AG, W1T + (size_t)l * 128 * 512, b1 + (size_t)l * 2 * DIM,
            nullptr, nullptr, nullptr, nullptr, MID, n);
        const float* g = gamma + (size_t)l * DIM;
        const float* bt = beta + (size_t)l * DIM;
        const float* mn = bnm + (size_t)l * DIM;
        const float* vr = bnv + (size_t)l * DIM;
        const float* W2Tl = W2T + (size_t)l * 256 * 256;
        const float* B2 = b2 + (size_t)l * DIM;
        if (l < NLAYER - 1) {
            k_gemm<256, 128, true, true><<<dim3(mblocks, 1), 256, GEMM_SMEM>>>(
                MID, W2Tl, B2, g, bt, mn, vr, H, n);
        } else {
            k_gemm<256, 128, true, false><<<dim3(mblocks, 1), 256, GEMM_SMEM>>>(
                MID, W2Tl, B2, g, bt, mn, vr, out, n);
        }
    }
}

// round 5
// speedup vs baseline: 1.7693x; 1.7693x over previous
#include <cuda_runtime.h>

#define N_NODES 100000
#define N_EDGES 1600000
#define DIM 128
#define NLAYER 5

// ---------------- scratch (device globals; no allocations) ----------------
__device__ float g_h[N_NODES * DIM];
__device__ float g_agg[N_NODES * DIM];
__device__ float g_mid[N_NODES * 2 * DIM];
__device__ int   g_rowptr[N_NODES + 1];
__device__ int   g_cursor[N_NODES];
__device__ int   g_cnt[N_NODES];
__device__ int   g_edge[N_EDGES];             // packed: src | combined_idx<<20
__device__ int   g_bsum[128];                 // block sums for hierarchical scan
__device__ int   g_boff[128];                 // block offsets

#define W1T_SZ (NLAYER * 128 * 256)           // [l][k][j] transposed, J=256
#define W2T_SZ (NLAYER * 256 * 128)           // [l][k][j] transposed, J=128
__device__ float g_w1t[W1T_SZ];
__device__ float g_w2t[W2T_SZ];

// ---------------- weight pre-transpose (no duplication) ----------------
__global__ void k_wt(const float* __restrict__ w1, const float* __restrict__ w2) {
    int i = blockIdx.x * blockDim.x + threadIdx.x;
    if (i < W1T_SZ) {
        int l = i >> 15;                       // /32768
        int r = i & 32767;
        int k = r >> 8, j = r & 255;
        g_w1t[i] = w1[((size_t)l * 256 + j) * 128 + k];
    }
    if (i < W2T_SZ) {
        int l = i >> 15;
        int r = i & 32767;
        int k = r >> 7, j = r & 127;
        g_w2t[i] = w2[((size_t)l * 128 + j) * 256 + k];
    }
}

// ---------------- CSR build ----------------
__global__ void k_zero_cnt(int n) {
    int i = blockIdx.x * blockDim.x + threadIdx.x;
    if (i < n) g_cnt[i] = 0;
}

__global__ void k_count(const int* __restrict__ dst, int E) {
    int e = blockIdx.x * blockDim.x + threadIdx.x;
    if (e < E) atomicAdd(&g_cnt[dst[e]], 1);
}

// hierarchical scan: per-block sums
__global__ void k_bsum(int n) {
    __shared__ int wsum[32];
    int i = blockIdx.x * 1024 + threadIdx.x;
    int lane = threadIdx.x & 31, wid = threadIdx.x >> 5;
    int v = (i < n) ? g_cnt[i] : 0;
    int s = v;
    #pragma unroll
    for (int o = 16; o > 0; o >>= 1) s += __shfl_down_sync(0xffffffffu, s, o);
    if (lane == 0) wsum[wid] = s;
    __syncthreads();
    if (wid == 0) {
        int t = wsum[lane];
        #pragma unroll
        for (int o = 16; o > 0; o >>= 1) t += __shfl_down_sync(0xffffffffu, t, o);
        if (lane == 0) g_bsum[blockIdx.x] = t;
    }
}

// scan the (<=128) block sums in one small block
__global__ void k_boff(int nblk) {
    __shared__ int ws[4];
    int lane = threadIdx.x & 31, wid = threadIdx.x >> 5;
    int v = (threadIdx.x < nblk) ? g_bsum[threadIdx.x] : 0;
    int s = v;
    #pragma unroll
    for (int o = 1; o < 32; o <<= 1) {
        int t = __shfl_up_sync(0xffffffffu, s, o);
        if (lane >= o) s += t;
    }
    if (lane == 31) ws[wid] = s;
    __syncthreads();
    if (wid == 0 && lane < 4) {
        int t = ws[lane];
        #pragma unroll
        for (int o = 1; o < 4; o <<= 1) {
            int u = __shfl_up_sync(0xfu, t, o);
            if (lane >= o) t += u;
        }
        ws[lane] = t;
    }
    __syncthreads();
    int excl = s - v + (wid ? ws[wid - 1] : 0);
    if (threadIdx.x < nblk) g_boff[threadIdx.x] = excl;
}

// local scan + add block offset -> rowptr, cursor
__global__ void k_local(int n) {
    __shared__ int wsum[32];
    int i = blockIdx.x * 1024 + threadIdx.x;
    int lane = threadIdx.x & 31, wid = threadIdx.x >> 5;
    int v = (i < n) ? g_cnt[i] : 0;
    int s = v;
    #pragma unroll
    for (int o = 1; o < 32; o <<= 1) {
        int t = __shfl_up_sync(0xffffffffu, s, o);
        if (lane >= o) s += t;
    }
    if (lane == 31) wsum[wid] = s;
    __syncthreads();
    if (wid == 0) {
        int t = wsum[lane];
        #pragma unroll
        for (int o = 1; o < 32; o <<= 1) {
            int u = __shfl_up_sync(0xffffffffu, t, o);
            if (lane >= o) t += u;
        }
        wsum[lane] = t;
    }
    __syncthreads();
    int excl = s - v + (wid ? wsum[wid - 1] : 0) + g_boff[blockIdx.x];
    if (i < n) {
        g_rowptr[i] = excl;
        g_cursor[i] = excl;
        if (i == n - 1) g_rowptr[n] = excl + v;
    }
}

__global__ void k_fill(const int* __restrict__ src, const int* __restrict__ dst,
                       const int* __restrict__ eattr, int E) {
    int e = blockIdx.x * blockDim.x + threadIdx.x;
    if (e >= E) return;
    int d = dst[e];
    int pos = atomicAdd(&g_cursor[d], 1);
    int ci = eattr[2 * e] * 3 + eattr[2 * e + 1];
    g_edge[pos] = src[e] | (ci << 20);
}

// ---------------- node input embedding ----------------
__global__ void k_embed(const int* __restrict__ x, const float* __restrict__ xemb, int n) {
    int i = blockIdx.x * blockDim.x + threadIdx.x;
    int v = i >> 5, c = (i & 31) * 4;
    if (v >= n) return;
    int a = x[2 * v], ch = x[2 * v + 1];
    float4 va = *(const float4*)(xemb + (size_t)a * DIM + c);
    float4 vb = *(const float4*)(xemb + (size_t)(120 + ch) * DIM + c);
    float4 r;
    r.x = va.x + vb.x; r.y = va.y + vb.y; r.z = va.z + vb.z; r.w = va.w + vb.w;
    *(float4*)(g_h + (size_t)v * DIM + c) = r;
}

// ---------------- aggregation: one warp per node, combined edge table ----------------
__global__ void k_agg(const float* __restrict__ etab_l, int n) {
    __shared__ float4 ctb[18 * 32];
    for (int i = threadIdx.x; i < 18 * 32; i += blockDim.x) {
        int comb = i >> 5, ln = i & 31;
        int eb = comb / 3, ed = comb - eb * 3;
        float4 b = ((const float4*)etab_l)[eb * 32 + ln];
        float4 d = ((const float4*)(etab_l + 6 * DIM))[ed * 32 + ln];
        ctb[i] = make_float4(b.x + d.x, b.y + d.y, b.z + d.z, b.w + d.w);
    }
    __syncthreads();
    int w = (blockIdx.x * blockDim.x + threadIdx.x) >> 5;
    int lane = threadIdx.x & 31;
    if (w >= n) return;
    int beg = g_rowptr[w], end = g_rowptr[w + 1];
    float4 acc0 = *(const float4*)(g_h + (size_t)w * DIM + lane * 4);
    {
        float4 sl = ctb[12 * 32 + lane];   // self-loop: bond 4, dir 0
        acc0.x += sl.x; acc0.y += sl.y; acc0.z += sl.z; acc0.w += sl.w;
    }
    float4 acc1 = make_float4(0.f, 0.f, 0.f, 0.f);
    float4 acc2 = make_float4(0.f, 0.f, 0.f, 0.f);
    float4 acc3 = make_float4(0.f, 0.f, 0.f, 0.f);
    int p = beg;
    for (; p + 4 <= end; p += 4) {
        int pk0 = g_edge[p], pk1 = g_edge[p + 1], pk2 = g_edge[p + 2], pk3 = g_edge[p + 3];
        float4 h0 = *(const float4*)(g_h + (size_t)(pk0 & 0xFFFFF) * DIM + lane * 4);
        float4 h1 = *(const float4*)(g_h + (size_t)(pk1 & 0xFFFFF) * DIM + lane * 4);
        float4 h2 = *(const float4*)(g_h + (size_t)(pk2 & 0xFFFFF) * DIM + lane * 4);
        float4 h3 = *(const float4*)(g_h + (size_t)(pk3 & 0xFFFFF) * DIM + lane * 4);
        float4 e0 = ctb[(pk0 >> 20) * 32 + lane];
        float4 e1 = ctb[(pk1 >> 20) * 32 + lane];
        float4 e2 = ctb[(pk2 >> 20) * 32 + lane];
        float4 e3 = ctb[(pk3 >> 20) * 32 + lane];
        acc0.x += h0.x + e0.x; acc0.y += h0.y + e0.y; acc0.z += h0.z + e0.z; acc0.w += h0.w + e0.w;
        acc1.x += h1.x + e1.x; acc1.y += h1.y + e1.y; acc1.z += h1.z + e1.z; acc1.w += h1.w + e1.w;
        acc2.x += h2.x + e2.x; acc2.y += h2.y + e2.y; acc2.z += h2.z + e2.z; acc2.w += h2.w + e2.w;
        acc3.x += h3.x + e3.x; acc3.y += h3.y + e3.y; acc3.z += h3.z + e3.z; acc3.w += h3.w + e3.w;
    }
    for (; p < end; p++) {
        int pk = g_edge[p];
        float4 hv = *(const float4*)(g_h + (size_t)(pk & 0xFFFFF) * DIM + lane * 4);
        float4 ev = ctb[(pk >> 20) * 32 + lane];
        acc0.x += hv.x + ev.x; acc0.y += hv.y + ev.y;
        acc0.z += hv.z + ev.z; acc0.w += hv.w + ev.w;
    }
    acc0.x += acc1.x + acc2.x + acc3.x;
    acc0.y += acc1.y + acc2.y + acc3.y;
    acc0.z += acc1.z + acc2.z + acc3.z;
    acc0.w += acc1.w + acc2.w + acc3.w;
    *(float4*)(g_agg + (size_t)w * DIM + lane * 4) = acc0;
}

// ---------------- GEMM: C[M,JTOT] = A[M,K] @ W[JTOT,K]^T ----------------
// Wt is the transposed weight [K][WROW] (WROW = total output cols, no dup).
// B staging: coalesced float2 load + duplicated float4 store (STS.128, 0 conflicts).
__device__ __forceinline__ void ffma2(unsigned long long& d, unsigned long long a,
                                      unsigned long long b) {
    asm("fma.rn.f32x2 %0, %1, %2, %0;" : "+l"(d) : "l"(a), "l"(b));
}

#define AS_STRIDE 130
#define BS_STRIDE 260
#define GEMM_SMEM ((64 * AS_STRIDE + 64 * BS_STRIDE) * 4)

template <int K, int JTOT, int WROW, bool BN, bool RELU>
__launch_bounds__(256, 2)
__global__ void k_gemm(const float* __restrict__ A, const float* __restrict__ Wt,
                       const float* __restrict__ bias,
                       const float* __restrict__ gamma, const float* __restrict__ beta,
                       const float* __restrict__ mean, const float* __restrict__ var,
                       float* __restrict__ C, int M) {
    extern __shared__ float sm[];
    float* As = sm;                      // [64][AS_STRIDE] k-major
    float* Bs = sm + 64 * AS_STRIDE;     // [64][BS_STRIDE] pair-duplicated
    int tid = threadIdx.x;
    int tc = tid & 15, tr = tid >> 4;
    int mb = blockIdx.x, jbase = blockIdx.y * 128;

    unsigned long long acc[32];
    #pragma unroll
    for (int i = 0; i < 32; i++) acc[i] = 0ull;

    for (int kb = 0; kb < K; kb += 64) {
        // stage A: 128 rows x 64 k, float2 loads (coalesced), 4-way-conflict stores
        #pragma unroll
        for (int t = 0; t < 16; t++) {
            int idx = tid + t * 256;          // 0..4095
            int kq2 = idx & 31;               // k-pair
            int row = idx >> 5;               // 0..127
            int rg = mb * 128 + row;
            float2 a = (rg < M) ? *(const float2*)(A + (size_t)rg * K + kb + kq2 * 2)
                                : make_float2(0.f, 0.f);
            As[(kq2 * 2) * AS_STRIDE + row]     = a.x;
            As[(kq2 * 2 + 1) * AS_STRIDE + row] = a.y;
        }
        // stage B: coalesced float2 load, duplicate into float4 store (no conflicts)
        #pragma unroll
        for (int t = 0; t < 16; t++) {
            int idx = tid + t * 256;          // 0..4095
            int f2 = idx & 63;                // column pair 0..63
            int k  = idx >> 6;                // 0..63
            float2 w = *(const float2*)(Wt + (size_t)(kb + k) * WROW + jbase + f2 * 2);
            *(float4*)(Bs + k * BS_STRIDE + f2 * 4) = make_float4(w.x, w.x, w.y, w.y);
        }
        __syncthreads();
        #pragma unroll 8
        for (int k = 0; k < 64; k++) {
            const unsigned long long* ap =
                (const unsigned long long*)(As + k * AS_STRIDE) + tr * 4;
            const unsigned long long* bp =
                (const unsigned long long*)(Bs + k * BS_STRIDE) + tc;
            unsigned long long a0 = ap[0], a1 = ap[1], a2 = ap[2], a3 = ap[3];
            unsigned long long b0 = bp[0],  b1 = bp[16],  b2 = bp[32],  b3 = bp[48];
            unsigned long long b4 = bp[64], b5 = bp[80],  b6 = bp[96],  b7 = bp[112];
            ffma2(acc[0],  a0, b0); ffma2(acc[1],  a0, b1);
            ffma2(acc[2],  a0, b2); ffma2(acc[3],  a0, b3);
            ffma2(acc[4],  a0, b4); ffma2(acc[5],  a0, b5);
            ffma2(acc[6],  a0, b6); ffma2(acc[7],  a0, b7);
            ffma2(acc[8],  a1, b0); ffma2(acc[9],  a1, b1);
            ffma2(acc[10], a1, b2); ffma2(acc[11], a1, b3);
            ffma2(acc[12], a1, b4); ffma2(acc[13], a1, b5);
            ffma2(acc[14], a1, b6); ffma2(acc[15], a1, b7);
            ffma2(acc[16], a2, b0); ffma2(acc[17], a2, b1);
            ffma2(acc[18], a2, b2); ffma2(acc[19], a2, b3);
            ffma2(acc[20], a2, b4); ffma2(acc[21], a2, b5);
            ffma2(acc[22], a2, b6); ffma2(acc[23], a2, b7);
            ffma2(acc[24], a3, b0); ffma2(acc[25], a3, b1);
            ffma2(acc[26], a3, b2); ffma2(acc[27], a3, b3);
            ffma2(acc[28], a3, b4); ffma2(acc[29], a3, b5);
            ffma2(acc[30], a3, b6); ffma2(acc[31], a3, b7);
        }
        __syncthreads();
    }

    // fused epilogue: bias (+ BN) (+ ReLU); thread's columns: jbase + c*16 + tc
    float cs[8], csh[8];
    #pragma unroll
    for (int c = 0; c < 8; c++) {
        int j = jbase + c * 16 + tc;
        if (BN) {
            float s = gamma[j] * rsqrtf(var[j] + 1e-5f);
            cs[c] = s;
            csh[c] = (bias[j] - mean[j]) * s + beta[j];
        } else {
            cs[c] = 1.f;
            csh[c] = bias[j];
        }
    }
    #pragma unroll
    for (int rp = 0; rp < 4; rp++) {
        #pragma unroll
        for (int h = 0; h < 2; h++) {
            int row = mb * 128 + tr * 8 + rp * 2 + h;
            if (row < M) {
                float* outp = C + (size_t)row * JTOT + jbase + tc;
                #pragma unroll
                for (int c = 0; c < 8; c++) {
                    unsigned long long u = acc[rp * 8 + c];
                    unsigned int bits = h ? (unsigned int)(u >> 32) : (unsigned int)u;
                    float v = __uint_as_float(bits);
                    v = v * cs[c] + csh[c];
                    if (RELU) v = fmaxf(v, 0.f);
                    outp[c * 16] = v;
                }
            }
        }
    }
}

// ---------------- launch ----------------
extern "C" void kernel_launch(void* const* d_in, const int* in_sizes, int n_in,
                              void* d_out, int out_size) {
    const int*   x     = (const int*)d_in[0];
    const int*   eidx  = (const int*)d_in[1];
    const int*   eattr = (const int*)d_in[2];
    const float* xemb  = (const float*)d_in[3];
    const float* etab  = (const float*)d_in[4];
    const float* w1    = (const float*)d_in[5];
    const float* b1    = (const float*)d_in[6];
    const float* w2    = (const float*)d_in[7];
    const float* b2    = (const float*)d_in[8];
    const float* gamma = (const float*)d_in[9];
    const float* beta  = (const float*)d_in[10];
    const float* bnm   = (const float*)d_in[11];
    const float* bnv   = (const float*)d_in[12];
    float* out = (float*)d_out;

    int n = in_sizes[0] / 2;
    int E = in_sizes[1] / 2;
    const int* srcp = eidx;
    const int* dstp = eidx + E;

    cudaFuncSetAttribute(k_gemm<128, 256, 256, false, true>,
                         cudaFuncAttributeMaxDynamicSharedMemorySize, GEMM_SMEM);
    cudaFuncSetAttribute(k_gemm<256, 128, 128, true, true>,
                         cudaFuncAttributeMaxDynamicSharedMemorySize, GEMM_SMEM);
    cudaFuncSetAttribute(k_gemm<256, 128, 128, true, false>,
                         cudaFuncAttributeMaxDynamicSharedMemorySize, GEMM_SMEM);

    void *ph, *pagg, *pmid, *pw1t, *pw2t;
    cudaGetSymbolAddress(&ph, g_h);
    cudaGetSymbolAddress(&pagg, g_agg);
    cudaGetSymbolAddress(&pmid, g_mid);
    cudaGetSymbolAddress(&pw1t, g_w1t);
    cudaGetSymbolAddress(&pw2t, g_w2t);
    float* H = (float*)ph;
    float* AG = (float*)pagg;
    float* MID = (float*)pmid;
    const float* W1T = (const float*)pw1t;
    const float* W2T = (const float*)pw2t;

    int nblk = (n + 1023) / 1024;

    // weight transpose + CSR build + embed
    k_wt<<<(W1T_SZ + 255) / 256, 256>>>(w1, w2);
    k_zero_cnt<<<(n + 255) / 256, 256>>>(n);
    k_count<<<(E + 255) / 256, 256>>>(dstp, E);
    k_bsum<<<nblk, 1024>>>(n);
    k_boff<<<1, 128>>>(nblk);
    k_local<<<nblk, 1024>>>(n);
    k_fill<<<(E + 255) / 256, 256>>>(srcp, dstp, eattr, E);
    k_embed<<<(n * 32 + 255) / 256, 256>>>(x, xemb, n);

    int mblocks = (n + 127) / 128;
    for (int l = 0; l < NLAYER; l++) {
        k_agg<<<(n * 32 + 255) / 256, 256>>>(etab + (size_t)l * 9 * DIM, n);
        k_gemm<128, 256, 256, false, true><<<dim3(mblocks, 2), 256, GEMM_SMEM>>>(
            AG, W1T + (size_t)l * 128 * 256, b1 + (size_t)l * 2 * DIM,
            nullptr, nullptr, nullptr, nullptr, MID, n);
        const float* g = gamma + (size_t)l * DIM;
        const float* bt = beta + (size_t)l * DIM;
        const float* mn = bnm + (size_t)l * DIM;
        const float* vr = bnv + (size_t)l * DIM;
        const float* W2Tl = W2T + (size_t)l * 256 * 128;
        const float* B2 = b2 + (size_t)l * DIM;
        if (l < NLAYER - 1) {
            k_gemm<256, 128, 128, true, true><<<dim3(mblocks, 1), 256, GEMM_SMEM>>>(
                MID, W2Tl, B2, g, bt, mn, vr, H, n);
        } else {
            k_gemm<256, 128, 128, true, false><<<dim3(mblocks, 1), 256, GEMM_SMEM>>>(
                MID, W2Tl, B2, g, bt, mn, vr, out, n);
        }
    }
}

// round 7
// speedup vs baseline: 3.0185x; 1.7060x over previous
#include <cuda_runtime.h>
#include <cuda_bf16.h>
#include <cstdint>

#define N_NODES 100000
#define N_EDGES 1600000
#define DIM 128
#define NLAYER 5

// ---------------- scratch (device globals; no allocations) ----------------
__device__ float g_h[N_NODES * DIM];
__device__ float g_agg[N_NODES * DIM];
__device__ float g_mid[N_NODES * 2 * DIM];
__device__ int   g_rowptr[N_NODES + 1];
__device__ int   g_cursor[N_NODES];
__device__ int   g_cnt[N_NODES];
__device__ int   g_edge[N_EDGES];             // packed: src | combined_idx<<20
__device__ int   g_bsum[128];
__device__ int   g_boff[128];

#define WSZ (NLAYER * 256 * 128)
__device__ __nv_bfloat16 g_w1h[WSZ];
__device__ __nv_bfloat16 g_w1l[WSZ];
__device__ __nv_bfloat16 g_w2h[WSZ];
__device__ __nv_bfloat16 g_w2l[WSZ];

// ---------------- weight split: fp32 -> bf16 hi + bf16 lo ----------------
__global__ void k_wt(const float* __restrict__ w1, const float* __restrict__ w2) {
    int i = blockIdx.x * blockDim.x + threadIdx.x;
    if (i >= WSZ) return;
    float a = w1[i];
    __nv_bfloat16 h = __float2bfloat16_rn(a);
    g_w1h[i] = h;
    g_w1l[i] = __float2bfloat16_rn(a - __bfloat162float(h));
    float b = w2[i];
    __nv_bfloat16 h2 = __float2bfloat16_rn(b);
    g_w2h[i] = h2;
    g_w2l[i] = __float2bfloat16_rn(b - __bfloat162float(h2));
}

// ---------------- CSR build ----------------
__global__ void k_zero_cnt(int n) {
    int i = blockIdx.x * blockDim.x + threadIdx.x;
    if (i < n) g_cnt[i] = 0;
}
__global__ void k_count(const int* __restrict__ dst, int E) {
    int e = blockIdx.x * blockDim.x + threadIdx.x;
    if (e < E) atomicAdd(&g_cnt[dst[e]], 1);
}
__global__ void k_bsum(int n) {
    __shared__ int wsum[32];
    int i = blockIdx.x * 1024 + threadIdx.x;
    int lane = threadIdx.x & 31, wid = threadIdx.x >> 5;
    int v = (i < n) ? g_cnt[i] : 0;
    int s = v;
    #pragma unroll
    for (int o = 16; o > 0; o >>= 1) s += __shfl_down_sync(0xffffffffu, s, o);
    if (lane == 0) wsum[wid] = s;
    __syncthreads();
    if (wid == 0) {
        int t = wsum[lane];
        #pragma unroll
        for (int o = 16; o > 0; o >>= 1) t += __shfl_down_sync(0xffffffffu, t, o);
        if (lane == 0) g_bsum[blockIdx.x] = t;
    }
}
__global__ void k_boff(int nblk) {
    __shared__ int ws[4];
    int lane = threadIdx.x & 31, wid = threadIdx.x >> 5;
    int v = (threadIdx.x < nblk) ? g_bsum[threadIdx.x] : 0;
    int s = v;
    #pragma unroll
    for (int o = 1; o < 32; o <<= 1) {
        int t = __shfl_up_sync(0xffffffffu, s, o);
        if (lane >= o) s += t;
    }
    if (lane == 31) ws[wid] = s;
    __syncthreads();
    if (wid == 0 && lane < 4) {
        int t = ws[lane];
        #pragma unroll
        for (int o = 1; o < 4; o <<= 1) {
            int u = __shfl_up_sync(0xfu, t, o);
            if (lane >= o) t += u;
        }
        ws[lane] = t;
    }
    __syncthreads();
    int excl = s - v + (wid ? ws[wid - 1] : 0);
    if (threadIdx.x < nblk) g_boff[threadIdx.x] = excl;
}
__global__ void k_local(int n) {
    __shared__ int wsum[32];
    int i = blockIdx.x * 1024 + threadIdx.x;
    int lane = threadIdx.x & 31, wid = threadIdx.x >> 5;
    int v = (i < n) ? g_cnt[i] : 0;
    int s = v;
    #pragma unroll
    for (int o = 1; o < 32; o <<= 1) {
        int t = __shfl_up_sync(0xffffffffu, s, o);
        if (lane >= o) s += t;
    }
    if (lane == 31) wsum[wid] = s;
    __syncthreads();
    if (wid == 0) {
        int t = wsum[lane];
        #pragma unroll
        for (int o = 1; o < 32; o <<= 1) {
            int u = __shfl_up_sync(0xffffffffu, t, o);
            if (lane >= o) t += u;
        }
        wsum[lane] = t;
    }
    __syncthreads();
    int excl = s - v + (wid ? wsum[wid - 1] : 0) + g_boff[blockIdx.x];
    if (i < n) {
        g_rowptr[i] = excl;
        g_cursor[i] = excl;
        if (i == n - 1) g_rowptr[n] = excl + v;
    }
}
__global__ void k_fill(const int* __restrict__ src, const int* __restrict__ dst,
                       const int* __restrict__ eattr, int E) {
    int e = blockIdx.x * blockDim.x + threadIdx.x;
    if (e >= E) return;
    int d = dst[e];
    int pos = atomicAdd(&g_cursor[d], 1);
    int ci = eattr[2 * e] * 3 + eattr[2 * e + 1];
    g_edge[pos] = src[e] | (ci << 20);
}

// ---------------- node input embedding ----------------
__global__ void k_embed(const int* __restrict__ x, const float* __restrict__ xemb, int n) {
    int i = blockIdx.x * blockDim.x + threadIdx.x;
    int v = i >> 5, c = (i & 31) * 4;
    if (v >= n) return;
    int a = x[2 * v], ch = x[2 * v + 1];
    float4 va = *(const float4*)(xemb + (size_t)a * DIM + c);
    float4 vb = *(const float4*)(xemb + (size_t)(120 + ch) * DIM + c);
    float4 r;
    r.x = va.x + vb.x; r.y = va.y + vb.y; r.z = va.z + vb.z; r.w = va.w + vb.w;
    *(float4*)(g_h + (size_t)v * DIM + c) = r;
}

// ---------------- aggregation: one warp per node ----------------
__global__ void k_agg(const float* __restrict__ etab_l, int n) {
    __shared__ float4 ctb[18 * 32];
    for (int i = threadIdx.x; i < 18 * 32; i += blockDim.x) {
        int comb = i >> 5, ln = i & 31;
        int eb = comb / 3, ed = comb - eb * 3;
        float4 b = ((const float4*)etab_l)[eb * 32 + ln];
        float4 d = ((const float4*)(etab_l + 6 * DIM))[ed * 32 + ln];
        ctb[i] = make_float4(b.x + d.x, b.y + d.y, b.z + d.z, b.w + d.w);
    }
    __syncthreads();
    int w = (blockIdx.x * blockDim.x + threadIdx.x) >> 5;
    int lane = threadIdx.x & 31;
    if (w >= n) return;
    int beg = g_rowptr[w], end = g_rowptr[w + 1];
    float4 acc0 = *(const float4*)(g_h + (size_t)w * DIM + lane * 4);
    {
        float4 sl = ctb[12 * 32 + lane];
        acc0.x += sl.x; acc0.y += sl.y; acc0.z += sl.z; acc0.w += sl.w;
    }
    float4 acc1 = make_float4(0.f, 0.f, 0.f, 0.f);
    float4 acc2 = make_float4(0.f, 0.f, 0.f, 0.f);
    float4 acc3 = make_float4(0.f, 0.f, 0.f, 0.f);
    int p = beg;
    for (; p + 4 <= end; p += 4) {
        int pk0 = g_edge[p], pk1 = g_edge[p + 1], pk2 = g_edge[p + 2], pk3 = g_edge[p + 3];
        float4 h0 = *(const float4*)(g_h + (size_t)(pk0 & 0xFFFFF) * DIM + lane * 4);
        float4 h1 = *(const float4*)(g_h + (size_t)(pk1 & 0xFFFFF) * DIM + lane * 4);
        float4 h2 = *(const float4*)(g_h + (size_t)(pk2 & 0xFFFFF) * DIM + lane * 4);
        float4 h3 = *(const float4*)(g_h + (size_t)(pk3 & 0xFFFFF) * DIM + lane * 4);
        float4 e0 = ctb[(pk0 >> 20) * 32 + lane];
        float4 e1 = ctb[(pk1 >> 20) * 32 + lane];
        float4 e2 = ctb[(pk2 >> 20) * 32 + lane];
        float4 e3 = ctb[(pk3 >> 20) * 32 + lane];
        acc0.x += h0.x + e0.x; acc0.y += h0.y + e0.y; acc0.z += h0.z + e0.z; acc0.w += h0.w + e0.w;
        acc1.x += h1.x + e1.x; acc1.y += h1.y + e1.y; acc1.z += h1.z + e1.z; acc1.w += h1.w + e1.w;
        acc2.x += h2.x + e2.x; acc2.y += h2.y + e2.y; acc2.z += h2.z + e2.z; acc2.w += h2.w + e2.w;
        acc3.x += h3.x + e3.x; acc3.y += h3.y + e3.y; acc3.z += h3.z + e3.z; acc3.w += h3.w + e3.w;
    }
    for (; p < end; p++) {
        int pk = g_edge[p];
        float4 hv = *(const float4*)(g_h + (size_t)(pk & 0xFFFFF) * DIM + lane * 4);
        float4 ev = ctb[(pk >> 20) * 32 + lane];
        acc0.x += hv.x + ev.x; acc0.y += hv.y + ev.y;
        acc0.z += hv.z + ev.z; acc0.w += hv.w + ev.w;
    }
    acc0.x += acc1.x + acc2.x + acc3.x;
    acc0.y += acc1.y + acc2.y + acc3.y;
    acc0.z += acc1.z + acc2.z + acc3.z;
    acc0.w += acc1.w + acc2.w + acc3.w;
    *(float4*)(g_agg + (size_t)w * DIM + lane * 4) = acc0;
}

// ---------------- mma.sync GEMM: C[M,JTOT] = A[M,KTOT] @ W[JTOT,KTOT]^T ----------------
// bf16 split: D = Ahi*Whi + Ahi*Wlo + Alo*Whi (fp32 accumulate).
// CTA tile 128x128, 8 warps (4m x 2n), warp tile 32x64, K chunk 64.
#define SROWB 144                          // smem row stride in bytes (72 bf16)
#define TILE_B (128 * SROWB)               // 18432 bytes per tile
#define OFF_SCALE 0
#define OFF_SHIFT 512
#define OFF_AHI 1024
#define OFF_ALO (OFF_AHI + TILE_B)
#define OFF_BHI (OFF_ALO + TILE_B)
#define OFF_BLO (OFF_BHI + TILE_B)
#define MMA_SMEM (OFF_BLO + TILE_B)        // 74752 bytes

__device__ __forceinline__ uint32_t smem_u32(const void* p) {
    uint32_t a;
    asm("{ .reg .u64 t; cvta.to.shared.u64 t, %1; cvt.u32.u64 %0, t; }" : "=r"(a) : "l"(p));
    return a;
}
__device__ __forceinline__ void ldsm4(uint32_t* r, uint32_t addr) {
    asm volatile("ldmatrix.sync.aligned.m8n8.x4.shared.b16 {%0,%1,%2,%3}, [%4];"
                 : "=r"(r[0]), "=r"(r[1]), "=r"(r[2]), "=r"(r[3]) : "r"(addr));
}
__device__ __forceinline__ void mma16816(float* d, const uint32_t* a,
                                         uint32_t b0, uint32_t b1) {
    asm volatile(
        "mma.sync.aligned.m16n8k16.row.col.f32.bf16.bf16.f32 "
        "{%0,%1,%2,%3}, {%4,%5,%6,%7}, {%8,%9}, {%0,%1,%2,%3};"
        : "+f"(d[0]), "+f"(d[1]), "+f"(d[2]), "+f"(d[3])
        : "r"(a[0]), "r"(a[1]), "r"(a[2]), "r"(a[3]), "r"(b0), "r"(b1));
}

template <int KTOT, int JTOT, bool BN, bool RELU>
__global__ void __launch_bounds__(256)
k_mma(const float* __restrict__ A,
      const __nv_bfloat16* __restrict__ Wh, const __nv_bfloat16* __restrict__ Wl,
      const float* __restrict__ bias,
      const float* __restrict__ gamma, const float* __restrict__ beta,
      const float* __restrict__ mean, const float* __restrict__ var,
      float* __restrict__ C, int M) {
    extern __shared__ char sm[];
    uint32_t sb = smem_u32(sm);
    float* s_scale = (float*)(sm + OFF_SCALE);
    float* s_shift = (float*)(sm + OFF_SHIFT);
    int tid = threadIdx.x;
    int wid = tid >> 5, lane = tid & 31;
    int mb = blockIdx.x, jbase = blockIdx.y * 128;
    int wm = wid >> 1, wn = wid & 1;       // warp tile: rows wm*32.., cols wn*64..

    if (tid < 128) {
        int j = jbase + tid;
        if (BN) {
            float s = gamma[j] * rsqrtf(var[j] + 1e-5f);
            s_scale[tid] = s;
            s_shift[tid] = (bias[j] - mean[j]) * s + beta[j];
        } else {
            s_scale[tid] = 1.f;
            s_shift[tid] = bias[j];
        }
    }

    float acc[2][8][4];
    #pragma unroll
    for (int a = 0; a < 2; a++)
        #pragma unroll
        for (int b = 0; b < 8; b++)
            #pragma unroll
            for (int c = 0; c < 4; c++) acc[a][b][c] = 0.f;

    // ldmatrix lane address components (same mapping for A and B):
    // lanes 0-15 -> rows r=lane, col k0; lanes 16-31 -> rows r=lane-16, col k0+8
    int lr = lane & 15, lc8 = lane >> 4;

    for (int kb = 0; kb < KTOT; kb += 64) {
        // ---- stage A (fp32 -> bf16 hi/lo): 128 rows x 64 k ----
        #pragma unroll
        for (int t = 0; t < 8; t++) {
            int idx = tid + t * 256;          // 0..2047
            int row = idx >> 4;
            int k4 = (idx & 15) * 4;
            int rg = mb * 128 + row;
            float4 a = (rg < M) ? *(const float4*)(A + (size_t)rg * KTOT + kb + k4)
                                : make_float4(0.f, 0.f, 0.f, 0.f);
            __nv_bfloat16 h0 = __float2bfloat16_rn(a.x);
            __nv_bfloat16 h1 = __float2bfloat16_rn(a.y);
            __nv_bfloat16 h2 = __float2bfloat16_rn(a.z);
            __nv_bfloat16 h3 = __float2bfloat16_rn(a.w);
            __nv_bfloat162 hp0 = {h0, h1}, hp1 = {h2, h3};
            __nv_bfloat162 lp0 = {__float2bfloat16_rn(a.x - __bfloat162float(h0)),
                                  __float2bfloat16_rn(a.y - __bfloat162float(h1))};
            __nv_bfloat162 lp1 = {__float2bfloat16_rn(a.z - __bfloat162float(h2)),
                                  __float2bfloat16_rn(a.w - __bfloat162float(h3))};
            uint32_t off = row * SROWB + k4 * 2;
            *(uint2*)(sm + OFF_AHI + off) = make_uint2(*(uint32_t*)&hp0, *(uint32_t*)&hp1);
            *(uint2*)(sm + OFF_ALO + off) = make_uint2(*(uint32_t*)&lp0, *(uint32_t*)&lp1);
        }
        // ---- stage B (pre-split bf16): 128 j x 64 k ----
        #pragma unroll
        for (int t = 0; t < 4; t++) {
            int idx = tid + t * 256;          // 0..1023
            int j = idx >> 3;
            int k8 = (idx & 7) * 8;
            size_t gsrc = (size_t)(jbase + j) * KTOT + kb + k8;
            uint32_t off = j * SROWB + k8 * 2;
            *(uint4*)(sm + OFF_BHI + off) = *(const uint4*)(Wh + gsrc);
            *(uint4*)(sm + OFF_BLO + off) = *(const uint4*)(Wl + gsrc);
        }
        __syncthreads();

        // ---- compute: 4 k-steps of 16 ----
        #pragma unroll
        for (int ks = 0; ks < 4; ks++) {
            uint32_t ah[2][4], al[2][4];
            #pragma unroll
            for (int mf = 0; mf < 2; mf++) {
                uint32_t aoff = (uint32_t)((wm * 32 + mf * 16 + lr) * SROWB +
                                           ks * 32 + lc8 * 16);
                ldsm4(ah[mf], sb + OFF_AHI + aoff);
                ldsm4(al[mf], sb + OFF_ALO + aoff);
            }
            #pragma unroll
            for (int p = 0; p < 4; p++) {
                uint32_t bh[4], bl[4];
                uint32_t boff = (uint32_t)((wn * 64 + p * 16 + lr) * SROWB +
                                           ks * 32 + lc8 * 16);
                ldsm4(bh, sb + OFF_BHI + boff);
                ldsm4(bl, sb + OFF_BLO + boff);
                #pragma unroll
                for (int mf = 0; mf < 2; mf++) {
                    mma16816(acc[mf][2 * p],     ah[mf], bh[0], bh[2]);
                    mma16816(acc[mf][2 * p],     ah[mf], bl[0], bl[2]);
                    mma16816(acc[mf][2 * p],     al[mf], bh[0], bh[2]);
                    mma16816(acc[mf][2 * p + 1], ah[mf], bh[1], bh[3]);
                    mma16816(acc[mf][2 * p + 1], ah[mf], bl[1], bl[3]);
                    mma16816(acc[mf][2 * p + 1], al[mf], bh[1], bh[3]);
                }
            }
        }
        __syncthreads();
    }

    // ---- epilogue: scale/shift (+ReLU), float2 stores ----
    #pragma unroll
    for (int mf = 0; mf < 2; mf++) {
        int row0 = mb * 128 + wm * 32 + mf * 16 + (lane >> 2);
        int row1 = row0 + 8;
        #pragma unroll
        for (int nf = 0; nf < 8; nf++) {
            int col = wn * 64 + nf * 8 + (lane & 3) * 2;
            float s0 = s_scale[col], s1 = s_scale[col + 1];
            float t0 = s_shift[col], t1 = s_shift[col + 1];
            float v0 = acc[mf][nf][0] * s0 + t0;
            float v1 = acc[mf][nf][1] * s1 + t1;
            float v2 = acc[mf][nf][2] * s0 + t0;
            float v3 = acc[mf][nf][3] * s1 + t1;
            if (RELU) {
                v0 = fmaxf(v0, 0.f); v1 = fmaxf(v1, 0.f);
                v2 = fmaxf(v2, 0.f); v3 = fmaxf(v3, 0.f);
            }
            if (row0 < M)
                *(float2*)(C + (size_t)row0 * JTOT + jbase + col) = make_float2(v0, v1);
            if (row1 < M)
                *(float2*)(C + (size_t)row1 * JTOT + jbase + col) = make_float2(v2, v3);
        }
    }
}

// ---------------- launch ----------------
extern "C" void kernel_launch(void* const* d_in, const int* in_sizes, int n_in,
                              void* d_out, int out_size) {
    const int*   x     = (const int*)d_in[0];
    const int*   eidx  = (const int*)d_in[1];
    const int*   eattr = (const int*)d_in[2];
    const float* xemb  = (const float*)d_in[3];
    const float* etab  = (const float*)d_in[4];
    const float* w1    = (const float*)d_in[5];
    const float* b1    = (const float*)d_in[6];
    const float* w2    = (const float*)d_in[7];
    const float* b2    = (const float*)d_in[8];
    const float* gamma = (const float*)d_in[9];
    const float* beta  = (const float*)d_in[10];
    const float* bnm   = (const float*)d_in[11];
    const float* bnv   = (const float*)d_in[12];
    float* out = (float*)d_out;

    int n = in_sizes[0] / 2;
    int E = in_sizes[1] / 2;
    const int* srcp = eidx;
    const int* dstp = eidx + E;

    cudaFuncSetAttribute(k_mma<128, 256, false, true>,
                         cudaFuncAttributeMaxDynamicSharedMemorySize, MMA_SMEM);
    cudaFuncSetAttribute(k_mma<256, 128, true, true>,
                         cudaFuncAttributeMaxDynamicSharedMemorySize, MMA_SMEM);
    cudaFuncSetAttribute(k_mma<256, 128, true, false>,
                         cudaFuncAttributeMaxDynamicSharedMemorySize, MMA_SMEM);

    void *ph, *pagg, *pmid, *p1h, *p1l, *p2h, *p2l;
    cudaGetSymbolAddress(&ph, g_h);
    cudaGetSymbolAddress(&pagg, g_agg);
    cudaGetSymbolAddress(&pmid, g_mid);
    cudaGetSymbolAddress(&p1h, g_w1h);
    cudaGetSymbolAddress(&p1l, g_w1l);
    cudaGetSymbolAddress(&p2h, g_w2h);
    cudaGetSymbolAddress(&p2l, g_w2l);
    float* H = (float*)ph;
    float* AG = (float*)pagg;
    float* MID = (float*)pmid;
    const __nv_bfloat16* W1H = (const __nv_bfloat16*)p1h;
    const __nv_bfloat16* W1L = (const __nv_bfloat16*)p1l;
    const __nv_bfloat16* W2H = (const __nv_bfloat16*)p2h;
    const __nv_bfloat16* W2L = (const __nv_bfloat16*)p2l;

    int nblk = (n + 1023) / 1024;

    k_wt<<<(WSZ + 255) / 256, 256>>>(w1, w2);
    k_zero_cnt<<<(n + 255) / 256, 256>>>(n);
    k_count<<<(E + 255) / 256, 256>>>(dstp, E);
    k_bsum<<<nblk, 1024>>>(n);
    k_boff<<<1, 128>>>(nblk);
    k_local<<<nblk, 1024>>>(n);
    k_fill<<<(E + 255) / 256, 256>>>(srcp, dstp, eattr, E);
    k_embed<<<(n * 32 + 255) / 256, 256>>>(x, xemb, n);

    int mblocks = (n + 127) / 128;
    for (int l = 0; l < NLAYER; l++) {
        k_agg<<<(n * 32 + 255) / 256, 256>>>(etab + (size_t)l * 9 * DIM, n);
        // GEMM1: [n,128] @ W1[256,128]^T -> MID [n,256], bias+ReLU
        k_mma<128, 256, false, true><<<dim3(mblocks, 2), 256, MMA_SMEM>>>(
            AG, W1H + (size_t)l * 256 * 128, W1L + (size_t)l * 256 * 128,
            b1 + (size_t)l * 2 * DIM,
            nullptr, nullptr, nullptr, nullptr, MID, n);
        // GEMM2: [n,256] @ W2[128,256]^T -> H/out, bias+BN(+ReLU)
        const float* g = gamma + (size_t)l * DIM;
        const float* bt = beta + (size_t)l * DIM;
        const float* mn = bnm + (size_t)l * DIM;
        const float* vr = bnv + (size_t)l * DIM;
        const __nv_bfloat16* W2Hl = W2H + (size_t)l * 128 * 256;
        const __nv_bfloat16* W2Ll = W2L + (size_t)l * 128 * 256;
        const float* B2 = b2 + (size_t)l * DIM;
        if (l < NLAYER - 1) {
            k_mma<256, 128, true, true><<<dim3(mblocks, 1), 256, MMA_SMEM>>>(
                MID, W2Hl, W2Ll, B2, g, bt, mn, vr, H, n);
        } else {
            k_mma<256, 128, true, false><<<dim3(mblocks, 1), 256, MMA_SMEM>>>(
                MID, W2Hl, W2Ll, B2, g, bt, mn, vr, out, n);
        }
    }
}